// round 1
// baseline (speedup 1.0000x reference)
#include <cuda_runtime.h>
#include <math.h>

#define D 64          // embedding dim (fixed by problem)
#define DTXT 384      // text dim (fixed by problem)

// Scratch ping-pong buffers for propagation (N up to 2M rows * 64 floats / ... cap 8M floats = 32MB each)
__device__ float g_bufA[8 * 1024 * 1024];
__device__ float g_bufB[8 * 1024 * 1024];

// -------------------- init: cur = emb, acc = emb, zbuf = 0 --------------------
__global__ void k_init(const float4* __restrict__ emb, float4* __restrict__ cur,
                       float4* __restrict__ acc, float4* __restrict__ zb, int n4) {
    int i = blockIdx.x * blockDim.x + threadIdx.x;
    if (i < n4) {
        float4 v = emb[i];
        cur[i] = v;
        acc[i] = v;
        zb[i]  = make_float4(0.f, 0.f, 0.f, 0.f);
    }
}

// -------------------- acc += src ; optionally zero zb --------------------
__global__ void k_acczero(float4* __restrict__ acc, const float4* __restrict__ src,
                          float4* __restrict__ zb, int n4) {
    int i = blockIdx.x * blockDim.x + threadIdx.x;
    if (i < n4) {
        float4 a = acc[i];
        float4 s = src[i];
        a.x += s.x; a.y += s.y; a.z += s.z; a.w += s.w;
        acc[i] = a;
        if (zb) zb[i] = make_float4(0.f, 0.f, 0.f, 0.f);
    }
}

// -------------------- SpMM: out[row[e]] += val[e] * x[col[e]] --------------------
// One thread per (edge, 16B chunk). Warp = 2 edges; gather is 2 contiguous 256B rows.
// Scatter uses vectorized red.global.add.v4.f32 (sm_90+) to quarter atomic lane-ops.
__global__ void k_spmm(const int* __restrict__ row, const int* __restrict__ col,
                       const float* __restrict__ val, const float* __restrict__ x,
                       float* __restrict__ out, int E) {
    unsigned gid = blockIdx.x * blockDim.x + threadIdx.x;
    unsigned e = gid >> 4;
    if (e >= (unsigned)E) return;
    unsigned c = gid & 15u;

    int   r  = __ldg(row + e);
    int   cl = __ldg(col + e);
    float v  = __ldg(val + e);

    float4 xv = __ldg(((const float4*)(x + (size_t)cl * D)) + c);
    float* dst = out + (size_t)r * D + c * 4;
    asm volatile("red.global.add.v4.f32 [%0], {%1,%2,%3,%4};"
                 :: "l"(dst), "f"(xv.x * v), "f"(xv.y * v), "f"(xv.z * v), "f"(xv.w * v)
                 : "memory");
}

// -------------------- Text GEMM (N x 384 @ 384 x 64 + b) fused with --------------------
// per-row l2norm of t AND of the propagated acc (already in `out`), then out = 0.5*(g/||g|| + t/||t||)
// Block: 256 threads, 64 rows x 64 cols per block, 4x4 register tile per thread.
__global__ void k_textfinal(const float* __restrict__ tm, const float* __restrict__ ta,
                            const float* __restrict__ W, const float* __restrict__ bias,
                            float* __restrict__ out, int N_M, int N_A) {
    __shared__ float As[64 * 64];   // 16KB: rows x k-chunk
    __shared__ float Bs[64 * 64];   // 16KB: k-chunk x 64 cols
    __shared__ float s_bias[64];
    __shared__ float s_nt[64];
    __shared__ float s_ng[64];

    const float* T;
    float* acc;
    int N;
    if (blockIdx.y == 0) { T = tm; acc = out;                       N = N_M; }
    else                 { T = ta; acc = out + (size_t)N_M * D;     N = N_A; }

    int r0 = blockIdx.x * 64;
    if (r0 >= N) return;

    int tid = threadIdx.x;
    int tc  = tid & 15;   // col group (4 cols)
    int tr  = tid >> 4;   // row group (4 rows)

    if (tid < 64) { s_bias[tid] = bias[tid]; s_nt[tid] = 0.f; s_ng[tid] = 0.f; }

    float accv[4][4];
    #pragma unroll
    for (int i = 0; i < 4; i++)
        #pragma unroll
        for (int j = 0; j < 4; j++) accv[i][j] = 0.f;

    const float4* Asv = (const float4*)As;
    const float4* Bsv = (const float4*)Bs;

    for (int k0 = 0; k0 < DTXT; k0 += 64) {
        // Load A tile: 64 rows x 64 k (1024 float4)
        #pragma unroll
        for (int j = 0; j < 4; j++) {
            int fi = tid + j * 256;       // 0..1023
            int rr = fi >> 4;
            int kq = fi & 15;
            int gr = r0 + rr;
            float4 v = (gr < N) ? __ldg(((const float4*)(T + (size_t)gr * DTXT + k0)) + kq)
                                : make_float4(0.f, 0.f, 0.f, 0.f);
            ((float4*)As)[fi] = v;
        }
        // Load B tile: 64 k x 64 cols (contiguous 16KB)
        #pragma unroll
        for (int j = 0; j < 4; j++) {
            int fi = tid + j * 256;
            ((float4*)Bs)[fi] = __ldg(((const float4*)(W + (size_t)k0 * D)) + fi);
        }
        __syncthreads();

        #pragma unroll
        for (int kk = 0; kk < 64; kk += 4) {
            float bb[4][4];
            #pragma unroll
            for (int q = 0; q < 4; q++) {
                float4 bv = Bsv[(kk + q) * 16 + tc];
                bb[q][0] = bv.x; bb[q][1] = bv.y; bb[q][2] = bv.z; bb[q][3] = bv.w;
            }
            #pragma unroll
            for (int i = 0; i < 4; i++) {
                float4 av = Asv[((tr * 4 + i) * 64 + kk) >> 2];
                float aa[4] = {av.x, av.y, av.z, av.w};
                #pragma unroll
                for (int q = 0; q < 4; q++)
                    #pragma unroll
                    for (int j = 0; j < 4; j++)
                        accv[i][j] += aa[q] * bb[q][j];
            }
        }
        __syncthreads();
    }

    // Epilogue: bias, row sumsq for t and g
    float tv[4][4], gv[4][4];
    #pragma unroll
    for (int i = 0; i < 4; i++) {
        int lr = tr * 4 + i;
        int gr = r0 + lr;
        bool ok = gr < N;
        float st = 0.f, sg = 0.f;
        #pragma unroll
        for (int j = 0; j < 4; j++) {
            int c = tc * 4 + j;
            float t = accv[i][j] + s_bias[c];
            tv[i][j] = t;
            st += t * t;
            float g = ok ? acc[(size_t)gr * D + c] : 0.f;
            gv[i][j] = g;
            sg += g * g;
        }
        if (ok) {
            atomicAdd(&s_nt[lr], st);
            atomicAdd(&s_ng[lr], sg);
        }
    }
    __syncthreads();

    #pragma unroll
    for (int i = 0; i < 4; i++) {
        int lr = tr * 4 + i;
        int gr = r0 + lr;
        if (gr >= N) continue;
        float int_ = 1.f / fmaxf(sqrtf(s_nt[lr]), 1e-12f);
        float ing  = 1.f / fmaxf(sqrtf(s_ng[lr]), 1e-12f);
        #pragma unroll
        for (int j = 0; j < 4; j++) {
            int c = tc * 4 + j;
            acc[(size_t)gr * D + c] = 0.5f * (gv[i][j] * ing + tv[i][j] * int_);
        }
    }
}

// -------------------- launch --------------------
extern "C" void kernel_launch(void* const* d_in, const int* in_sizes, int n_in,
                              void* d_out, int out_size) {
    const int*   m_row = (const int*)d_in[0];
    const int*   m_col = (const int*)d_in[1];
    const float* m_val = (const float*)d_in[2];
    const int*   a_row = (const int*)d_in[3];
    const int*   a_col = (const int*)d_in[4];
    const float* a_val = (const float*)d_in[5];
    const float* m_txt = (const float*)d_in[6];
    const float* a_txt = (const float*)d_in[7];
    const float* m_emb = (const float*)d_in[8];
    const float* a_emb = (const float*)d_in[9];
    const float* W     = (const float*)d_in[10];
    const float* bias  = (const float*)d_in[11];

    int E_M = in_sizes[0];
    int E_A = in_sizes[3];
    int N_M = in_sizes[8] / D;
    int N_A = in_sizes[9] / D;

    float* out = (float*)d_out;

    float *bufA, *bufB;
    cudaGetSymbolAddress((void**)&bufA, g_bufA);
    cudaGetSymbolAddress((void**)&bufB, g_bufB);

    const int TB = 256;

    // --- graph propagation: 3 layers, acc = emb + x1 + x2 + x3 accumulated into out ---
    auto run_graph = [&](const int* row, const int* col, const float* val,
                         const float* emb, float* accout, int N, int E) {
        int n4 = N * (D / 4);
        int gb = (n4 + TB - 1) / TB;
        long long tot = (long long)E * 16;
        int sg = (int)((tot + TB - 1) / TB);

        k_init<<<gb, TB>>>((const float4*)emb, (float4*)bufA, (float4*)accout, (float4*)bufB, n4);
        k_spmm<<<sg, TB>>>(row, col, val, bufA, bufB, E);                       // x1 in B
        k_acczero<<<gb, TB>>>((float4*)accout, (const float4*)bufB, (float4*)bufA, n4);
        k_spmm<<<sg, TB>>>(row, col, val, bufB, bufA, E);                       // x2 in A
        k_acczero<<<gb, TB>>>((float4*)accout, (const float4*)bufA, (float4*)bufB, n4);
        k_spmm<<<sg, TB>>>(row, col, val, bufA, bufB, E);                       // x3 in B
        k_acczero<<<gb, TB>>>((float4*)accout, (const float4*)bufB, (float4*)0, n4);
    };

    run_graph(m_row, m_col, m_val, m_emb, out,                  N_M, E_M);
    run_graph(a_row, a_col, a_val, a_emb, out + (size_t)N_M * D, N_A, E_A);

    // --- text GEMM + fused l2norms + combine (both graphs via blockIdx.y) ---
    int maxN = (N_M > N_A) ? N_M : N_A;
    dim3 grid((maxN + 63) / 64, 2);
    k_textfinal<<<grid, 256>>>(m_txt, a_txt, W, bias, out, N_M, N_A);
}

// round 2
// speedup vs baseline: 1.2858x; 1.2858x over previous
#include <cuda_runtime.h>
#include <math.h>

#define D 64
#define DTXT 384
typedef unsigned long long ull;

#define MAXE (4 * 1024 * 1024)
#define MAXN 131072

// Scratch (static __device__ per harness rules)
__device__ ull   g_edges[MAXE];          // packed (val<<32 | col), sorted by row
__device__ float g_bufA[MAXN * D];       // 32MB ping
__device__ float g_bufB[MAXN * D];       // 32MB pong
__device__ int   g_rowptr[MAXN + 1];
__device__ int   g_cursor[MAXN];         // counts, then scatter cursors

// -------------------- histogram: cursor[row[e]]++ --------------------
__global__ void k_hist(const int* __restrict__ row, int* __restrict__ cnt, int E) {
    int e = blockIdx.x * blockDim.x + threadIdx.x;
    if (e < E) atomicAdd(&cnt[__ldg(row + e)], 1);
}

// -------------------- single-block exclusive scan over N counts --------------------
// Writes rowptr[0..N] and cursor[0..N-1] (= rowptr copy). cnt aliases cursor.
__global__ void k_scan(const int* __restrict__ cnt, int* __restrict__ rowptr,
                       int* __restrict__ cursor, int N) {
    __shared__ int sp[1024];
    int tid = threadIdx.x;
    int chunk = (N + 1023) >> 10;
    int s = tid * chunk;
    int e = min(s + chunk, N);
    int sum = 0;
    for (int i = s; i < e; i++) sum += cnt[i];
    sp[tid] = sum;
    __syncthreads();
    // inclusive Hillis-Steele scan over 1024 partials
    for (int off = 1; off < 1024; off <<= 1) {
        int v = (tid >= off) ? sp[tid - off] : 0;
        __syncthreads();
        sp[tid] += v;
        __syncthreads();
    }
    int excl = (tid == 0) ? 0 : sp[tid - 1];
    for (int i = s; i < e; i++) {
        int c = cnt[i];          // read BEFORE overwrite (cnt aliases cursor)
        rowptr[i] = excl;
        cursor[i] = excl;
        excl += c;
    }
    if (tid == 0) rowptr[N] = sp[1023];
}

// -------------------- scatter edges into row-sorted order --------------------
__global__ void k_scatter(const int* __restrict__ row, const int* __restrict__ col,
                          const float* __restrict__ val, int* __restrict__ cursor,
                          ull* __restrict__ edges, int E) {
    int e = blockIdx.x * blockDim.x + threadIdx.x;
    if (e < E) {
        int r = __ldg(row + e);
        int pos = atomicAdd(&cursor[r], 1);
        ull p = ((ull)__float_as_uint(__ldg(val + e)) << 32) | (unsigned)__ldg(col + e);
        edges[pos] = p;
    }
}

// -------------------- CSR SpMM, warp per row, fused acc accumulation --------------------
// xnew[r] = sum_{e in row r} val[e] * x[col[e]]   (written iff xnew != null)
// accout[r] = accin[r] + xnew[r]
__global__ void k_spmm_csr(const ull* __restrict__ edges, const int* __restrict__ rowptr,
                           const float* __restrict__ x, const float* __restrict__ accin,
                           float* __restrict__ xnew, float* __restrict__ accout, int N) {
    int r = (blockIdx.x * blockDim.x + threadIdx.x) >> 5;
    if (r >= N) return;
    int lane = threadIdx.x & 31;

    int s = __ldg(rowptr + r);
    int e = __ldg(rowptr + r + 1);

    float ax = 0.f, ay = 0.f;
    #pragma unroll 4
    for (int i = s; i < e; i++) {
        ull p = __ldg(edges + i);                       // uniform broadcast, L1-hit
        int c = (int)(unsigned)p;
        float v = __uint_as_float((unsigned)(p >> 32));
        float2 xv = __ldg((const float2*)(x + (size_t)c * D) + lane);
        ax = fmaf(v, xv.x, ax);
        ay = fmaf(v, xv.y, ay);
    }

    float2 base = __ldg((const float2*)(accin + (size_t)r * D) + lane);
    if (xnew) ((float2*)(xnew + (size_t)r * D))[lane] = make_float2(ax, ay);
    ((float2*)(accout + (size_t)r * D))[lane] = make_float2(base.x + ax, base.y + ay);
}

// -------------------- Text GEMM + fused l2norm(t), l2norm(g), 0.5*(g+t) --------------------
__global__ void k_textfinal(const float* __restrict__ tm, const float* __restrict__ ta,
                            const float* __restrict__ W, const float* __restrict__ bias,
                            float* __restrict__ out, int N_M, int N_A) {
    __shared__ float As[64 * 64];
    __shared__ float Bs[64 * 64];
    __shared__ float s_bias[64];
    __shared__ float s_nt[64];
    __shared__ float s_ng[64];

    const float* T;
    float* acc;
    int N;
    if (blockIdx.y == 0) { T = tm; acc = out;                   N = N_M; }
    else                 { T = ta; acc = out + (size_t)N_M * D; N = N_A; }

    int r0 = blockIdx.x * 64;
    if (r0 >= N) return;

    int tid = threadIdx.x;
    int tc  = tid & 15;
    int tr  = tid >> 4;

    if (tid < 64) { s_bias[tid] = bias[tid]; s_nt[tid] = 0.f; s_ng[tid] = 0.f; }

    float accv[4][4];
    #pragma unroll
    for (int i = 0; i < 4; i++)
        #pragma unroll
        for (int j = 0; j < 4; j++) accv[i][j] = 0.f;

    const float4* Asv = (const float4*)As;
    const float4* Bsv = (const float4*)Bs;

    for (int k0 = 0; k0 < DTXT; k0 += 64) {
        #pragma unroll
        for (int j = 0; j < 4; j++) {
            int fi = tid + j * 256;
            int rr = fi >> 4;
            int kq = fi & 15;
            int gr = r0 + rr;
            float4 v = (gr < N) ? __ldg(((const float4*)(T + (size_t)gr * DTXT + k0)) + kq)
                                : make_float4(0.f, 0.f, 0.f, 0.f);
            ((float4*)As)[fi] = v;
        }
        #pragma unroll
        for (int j = 0; j < 4; j++) {
            int fi = tid + j * 256;
            ((float4*)Bs)[fi] = __ldg(((const float4*)(W + (size_t)k0 * D)) + fi);
        }
        __syncthreads();

        #pragma unroll
        for (int kk = 0; kk < 64; kk += 4) {
            float bb[4][4];
            #pragma unroll
            for (int q = 0; q < 4; q++) {
                float4 bv = Bsv[(kk + q) * 16 + tc];
                bb[q][0] = bv.x; bb[q][1] = bv.y; bb[q][2] = bv.z; bb[q][3] = bv.w;
            }
            #pragma unroll
            for (int i = 0; i < 4; i++) {
                float4 av = Asv[((tr * 4 + i) * 64 + kk) >> 2];
                float aa[4] = {av.x, av.y, av.z, av.w};
                #pragma unroll
                for (int q = 0; q < 4; q++)
                    #pragma unroll
                    for (int j = 0; j < 4; j++)
                        accv[i][j] += aa[q] * bb[q][j];
            }
        }
        __syncthreads();
    }

    float tv[4][4], gv[4][4];
    #pragma unroll
    for (int i = 0; i < 4; i++) {
        int lr = tr * 4 + i;
        int gr = r0 + lr;
        bool ok = gr < N;
        float st = 0.f, sg = 0.f;
        #pragma unroll
        for (int j = 0; j < 4; j++) {
            int c = tc * 4 + j;
            float t = accv[i][j] + s_bias[c];
            tv[i][j] = t;
            st += t * t;
            float g = ok ? acc[(size_t)gr * D + c] : 0.f;
            gv[i][j] = g;
            sg += g * g;
        }
        if (ok) {
            atomicAdd(&s_nt[lr], st);
            atomicAdd(&s_ng[lr], sg);
        }
    }
    __syncthreads();

    #pragma unroll
    for (int i = 0; i < 4; i++) {
        int lr = tr * 4 + i;
        int gr = r0 + lr;
        if (gr >= N) continue;
        float int_ = 1.f / fmaxf(sqrtf(s_nt[lr]), 1e-12f);
        float ing  = 1.f / fmaxf(sqrtf(s_ng[lr]), 1e-12f);
        #pragma unroll
        for (int j = 0; j < 4; j++) {
            int c = tc * 4 + j;
            acc[(size_t)gr * D + c] = 0.5f * (gv[i][j] * ing + tv[i][j] * int_);
        }
    }
}

// -------------------- launch --------------------
extern "C" void kernel_launch(void* const* d_in, const int* in_sizes, int n_in,
                              void* d_out, int out_size) {
    const int*   m_row = (const int*)d_in[0];
    const int*   m_col = (const int*)d_in[1];
    const float* m_val = (const float*)d_in[2];
    const int*   a_row = (const int*)d_in[3];
    const int*   a_col = (const int*)d_in[4];
    const float* a_val = (const float*)d_in[5];
    const float* m_txt = (const float*)d_in[6];
    const float* a_txt = (const float*)d_in[7];
    const float* m_emb = (const float*)d_in[8];
    const float* a_emb = (const float*)d_in[9];
    const float* W     = (const float*)d_in[10];
    const float* bias  = (const float*)d_in[11];

    int E_M = in_sizes[0];
    int E_A = in_sizes[3];
    int N_M = in_sizes[8] / D;
    int N_A = in_sizes[9] / D;

    float* out = (float*)d_out;

    ull*   edges;  cudaGetSymbolAddress((void**)&edges,  g_edges);
    float* bufA;   cudaGetSymbolAddress((void**)&bufA,   g_bufA);
    float* bufB;   cudaGetSymbolAddress((void**)&bufB,   g_bufB);
    int*   rowptr; cudaGetSymbolAddress((void**)&rowptr, g_rowptr);
    int*   cursor; cudaGetSymbolAddress((void**)&cursor, g_cursor);

    const int TB = 256;

    auto run_graph = [&](const int* row, const int* col, const float* val,
                         const float* emb, float* accout, int N, int E) {
        int eg = (E + TB - 1) / TB;
        int sg = (N * 32 + TB - 1) / TB;   // warp per row

        // build CSR
        cudaMemsetAsync(cursor, 0, (size_t)N * sizeof(int));
        k_hist<<<eg, TB>>>(row, cursor, E);
        k_scan<<<1, 1024>>>(cursor, rowptr, cursor, N);
        k_scatter<<<eg, TB>>>(row, col, val, cursor, edges, E);

        // 3 propagation layers, acc fused
        k_spmm_csr<<<sg, TB>>>(edges, rowptr, emb,  emb,    bufA,         accout, N); // acc = emb + x1
        k_spmm_csr<<<sg, TB>>>(edges, rowptr, bufA, accout, bufB,         accout, N); // acc += x2
        k_spmm_csr<<<sg, TB>>>(edges, rowptr, bufB, accout, (float*)0,    accout, N); // acc += x3
    };

    run_graph(m_row, m_col, m_val, m_emb, out,                   N_M, E_M);
    run_graph(a_row, a_col, a_val, a_emb, out + (size_t)N_M * D, N_A, E_A);

    int maxN = (N_M > N_A) ? N_M : N_A;
    dim3 grid((maxN + 63) / 64, 2);
    k_textfinal<<<grid, 256>>>(m_txt, a_txt, W, bias, out, N_M, N_A);
}